// round 11
// baseline (speedup 1.0000x reference)
#include <cuda_runtime.h>
#include <cstdint>
#include <cstddef>

// Problem constants (shapes fixed by the dataset)
#define NODES_MAX 100000
#define GRAPHS 64
#define EPS 1e-5f

// -------- scratch (static __device__ arrays; no allocation allowed) --------
__device__ float d_agg[(size_t)NODES_MAX * 128];
__device__ float d_h1 [(size_t)NODES_MAX * 128];
__device__ float d_h2 [(size_t)NODES_MAX * 128];
__device__ float d_cnt [NODES_MAX];
__device__ float d_invc[NODES_MAX];

// ---------------------------------------------------------------------------
// zero-fill (float4 granularity; all our sizes are multiples of 4 floats)
// ---------------------------------------------------------------------------
__global__ void zero4_kernel(float4* __restrict__ p, size_t n4) {
    size_t i = (size_t)blockIdx.x * blockDim.x + threadIdx.x;
    size_t stride = (size_t)gridDim.x * blockDim.x;
    float4 z = make_float4(0.f, 0.f, 0.f, 0.f);
    for (; i < n4; i += stride) p[i] = z;
}

// ---------------------------------------------------------------------------
// Layer-0 edge scatter: agg[dst, 0:7] += x[src, 0:7]; cnt[dst] += 1
// One thread per edge (din = 7). edge_index delivered as int32 by harness.
// ---------------------------------------------------------------------------
__global__ void scatter7_kernel(const float* __restrict__ x,
                                const int* __restrict__ ei, int E, int n) {
    int e = blockIdx.x * blockDim.x + threadIdx.x;
    if (e >= E) return;
    int s = ei[e];
    int d = ei[(size_t)E + e];
    if ((unsigned)s >= (unsigned)n || (unsigned)d >= (unsigned)n) return; // defensive
    const float* xr = x + (size_t)s * 7;
    float* a = d_agg + (size_t)d * 7;
#pragma unroll
    for (int k = 0; k < 7; k++) atomicAdd(a + k, xr[k]);
    atomicAdd(&d_cnt[d], 1.0f);
}

// ---------------------------------------------------------------------------
// din=128 edge scatter: one warp per edge; lane handles 4 consecutive floats.
// ---------------------------------------------------------------------------
__global__ void scatter128_kernel(const float* __restrict__ feat,
                                  const int* __restrict__ ei, int E, int n) {
    int idx = blockIdx.x * blockDim.x + threadIdx.x;
    int e = idx >> 5;
    int lane = idx & 31;
    if (e >= E) return;
    int s = ei[e];
    int d = ei[(size_t)E + e];
    if ((unsigned)s >= (unsigned)n || (unsigned)d >= (unsigned)n) return; // defensive
    float4 v = reinterpret_cast<const float4*>(feat + (size_t)s * 128)[lane];
    float* a = d_agg + (size_t)d * 128 + lane * 4;
    atomicAdd(a + 0, v.x);
    atomicAdd(a + 1, v.y);
    atomicAdd(a + 2, v.z);
    atomicAdd(a + 3, v.w);
}

// ---------------------------------------------------------------------------
// invc[i] = 1 / max(cnt[i], 1)
// ---------------------------------------------------------------------------
__global__ void invc_kernel(int n) {
    int i = blockIdx.x * blockDim.x + threadIdx.x;
    if (i < n) d_invc[i] = 1.0f / fmaxf(d_cnt[i], 1.0f);
}

// ---------------------------------------------------------------------------
// Layer 0: din=7 -> dout=128. One block (128 threads) per node.
//   h1 = relu(BN(x@Wl0 + bl0 + mean@Wr0))
// ---------------------------------------------------------------------------
__global__ void gemm0_kernel(const float* __restrict__ x,
                             const float* __restrict__ Wl, const float* __restrict__ bl,
                             const float* __restrict__ Wr,
                             const float* __restrict__ g,  const float* __restrict__ be,
                             const float* __restrict__ rm, const float* __restrict__ rv,
                             int n) {
    int node = blockIdx.x;
    int j = threadIdx.x;  // 0..127
    __shared__ float sx[7];
    __shared__ float sm[7];
    if (j < 7) {
        sx[j] = x[(size_t)node * 7 + j];
        sm[j] = d_agg[(size_t)node * 7 + j] * d_invc[node];
    }
    __syncthreads();
    float acc = bl[j];
#pragma unroll
    for (int k = 0; k < 7; k++)
        acc += sx[k] * Wl[k * 128 + j] + sm[k] * Wr[k * 128 + j];
    float s = g[j] * rsqrtf(rv[j] + EPS);
    float v = (acc - rm[j]) * s + be[j];
    d_h1[(size_t)node * 128 + j] = fmaxf(v, 0.0f);
}

// ---------------------------------------------------------------------------
// Main SGEMM for layers 1/2 (din=128).
//   C = relu(BN(A@Wl + bl + (agg*invc)@Wr))
// Tiling: BM=128, BN=128, BK=8, 256 threads, 8x8 register blocking.
// K-loop runs in two phases: phase 0 reads A with Wl; phase 1 reads
// d_agg scaled by invc[row] with Wr (implicit [x|mean]@[Wl;Wr], K=256).
// ---------------------------------------------------------------------------
template <int DOUT>
__global__ void __launch_bounds__(256, 2)
gemm_sage_kernel(const float* __restrict__ A,
                 const float* __restrict__ Wl, const float* __restrict__ Wr,
                 const float* __restrict__ bl,
                 const float* __restrict__ g,  const float* __restrict__ be,
                 const float* __restrict__ rm, const float* __restrict__ rv,
                 float* __restrict__ C, int n) {
    const int BM = 128, BN = 128, BK = 8;
    __shared__ __align__(16) float As[BK][136];   // padded; 136*4B keeps rows 16B-aligned
    __shared__ __align__(16) float Bs[BK][BN];
    __shared__ float sInv[BM];

    int tid  = threadIdx.x;
    int row0 = blockIdx.x * BM;
    int col0 = blockIdx.y * BN;

    if (tid < BM) {
        int r = row0 + tid;
        sInv[tid] = (r < n) ? d_invc[r] : 0.0f;
    }
    __syncthreads();

    // loader mapping
    int aRow = tid >> 1;            // 0..127
    int aK   = (tid & 1) << 2;      // 0 or 4
    int bK   = tid >> 5;            // 0..7
    int bJ   = (tid & 31) << 2;     // 0..124

    // compute mapping
    int tm0 = (tid >> 4) << 3;      // 0..120
    int tn0 = (tid & 15) << 3;      // 0..120

    int arow_g   = row0 + aRow;
    bool aValid  = arow_g < n;
    float scA    = sInv[aRow];

    float acc[8][8];
#pragma unroll
    for (int i = 0; i < 8; i++)
#pragma unroll
        for (int j = 0; j < 8; j++) acc[i][j] = 0.0f;

#pragma unroll 1
    for (int p = 0; p < 2; ++p) {
        const float* __restrict__ P = p ? (const float*)d_agg : A;
        const float* __restrict__ W = p ? Wr : Wl;
#pragma unroll 1
        for (int kk = 0; kk < 128 / BK; ++kk) {
            // ---- load A tile (transposed into smem) ----
            float4 v = make_float4(0.f, 0.f, 0.f, 0.f);
            if (aValid)
                v = *reinterpret_cast<const float4*>(P + (size_t)arow_g * 128 + kk * BK + aK);
            if (p) { v.x *= scA; v.y *= scA; v.z *= scA; v.w *= scA; }
            As[aK + 0][aRow] = v.x;
            As[aK + 1][aRow] = v.y;
            As[aK + 2][aRow] = v.z;
            As[aK + 3][aRow] = v.w;
            // ---- load B tile ----
            float4 w4 = *reinterpret_cast<const float4*>(
                W + (size_t)(kk * BK + bK) * DOUT + col0 + bJ);
            *reinterpret_cast<float4*>(&Bs[bK][bJ]) = w4;
            __syncthreads();
            // ---- compute ----
#pragma unroll
            for (int k = 0; k < BK; k++) {
                float a[8], b[8];
                *(float4*)&a[0] = *(const float4*)&As[k][tm0];
                *(float4*)&a[4] = *(const float4*)&As[k][tm0 + 4];
                *(float4*)&b[0] = *(const float4*)&Bs[k][tn0];
                *(float4*)&b[4] = *(const float4*)&Bs[k][tn0 + 4];
#pragma unroll
                for (int i = 0; i < 8; i++)
#pragma unroll
                    for (int j = 0; j < 8; j++) acc[i][j] += a[i] * b[j];
            }
            __syncthreads();
        }
    }

    // ---- epilogue: fold bias + eval-mode BN + ReLU ----
    float sj[8], tj[8];
#pragma unroll
    for (int j = 0; j < 8; j++) {
        int col = col0 + tn0 + j;
        float s = g[col] * rsqrtf(rv[col] + EPS);
        sj[j] = s;
        tj[j] = be[col] + (bl[col] - rm[col]) * s;
    }
#pragma unroll
    for (int i = 0; i < 8; i++) {
        int r = row0 + tm0 + i;
        if (r < n) {
            float* crow = C + (size_t)r * DOUT + col0 + tn0;
#pragma unroll
            for (int j = 0; j < 8; j++)
                crow[j] = fmaxf(acc[i][j] * sj[j] + tj[j], 0.0f);
        }
    }
}

// ---------------------------------------------------------------------------
// global_add_pool: batch is SORTED, so each thread owns one feature column,
// walks a row-chunk accumulating in a register, and flushes one atomic per
// graph boundary. batch delivered as int32 by harness.
// ---------------------------------------------------------------------------
#define POOL_ROWS 512
__global__ void pool_kernel(const float* __restrict__ xf,
                            const int* __restrict__ batch,
                            float* __restrict__ pooled, int n) {
    int j  = threadIdx.x;                 // 0..255 feature column
    int r0 = blockIdx.x * POOL_ROWS;
    if (r0 >= n) return;
    int r1 = min(r0 + POOL_ROWS, n);
    int cur = batch[r0];
    float acc = 0.0f;
    for (int r = r0; r < r1; ++r) {
        int b = batch[r];                 // uniform across block -> broadcast
        if (b != cur) {
            if ((unsigned)cur < GRAPHS) atomicAdd(&pooled[cur * 256 + j], acc);
            acc = 0.0f;
            cur = b;
        }
        acc += xf[(size_t)r * 256 + j];
    }
    if ((unsigned)cur < GRAPHS) atomicAdd(&pooled[cur * 256 + j], acc);
}

// ---------------------------------------------------------------------------
// launch
// ---------------------------------------------------------------------------
extern "C" void kernel_launch(void* const* d_in, const int* in_sizes, int n_in,
                              void* d_out, int out_size) {
    const float* x     = (const float*)d_in[0];
    const int*   ei    = (const int*)d_in[1];     // int64 in reference -> int32 in harness
    const int*   batch = (const int*)d_in[2];

    const float* Wl0 = (const float*)d_in[3];
    const float* bl0 = (const float*)d_in[4];
    const float* Wr0 = (const float*)d_in[5];
    const float* g0  = (const float*)d_in[6];
    const float* be0 = (const float*)d_in[7];
    const float* rm0 = (const float*)d_in[8];
    const float* rv0 = (const float*)d_in[9];

    const float* Wl1 = (const float*)d_in[10];
    const float* bl1 = (const float*)d_in[11];
    const float* Wr1 = (const float*)d_in[12];
    const float* g1  = (const float*)d_in[13];
    const float* be1 = (const float*)d_in[14];
    const float* rm1 = (const float*)d_in[15];
    const float* rv1 = (const float*)d_in[16];

    const float* Wl2 = (const float*)d_in[17];
    const float* bl2 = (const float*)d_in[18];
    const float* Wr2 = (const float*)d_in[19];
    const float* g2  = (const float*)d_in[20];
    const float* be2 = (const float*)d_in[21];
    const float* rm2 = (const float*)d_in[22];
    const float* rv2 = (const float*)d_in[23];

    const int E = in_sizes[1] / 2;
    const int n = in_sizes[2];

    float* out    = (float*)d_out;
    float* pooled = out;                        // [64, 256]
    float* xout   = out + (size_t)GRAPHS * 256; // [n, 256]

    float *agg = nullptr, *h1 = nullptr, *h2 = nullptr, *cnt = nullptr;
    cudaGetSymbolAddress((void**)&agg, d_agg);
    cudaGetSymbolAddress((void**)&h1,  d_h1);
    cudaGetSymbolAddress((void**)&h2,  d_h2);
    cudaGetSymbolAddress((void**)&cnt, d_cnt);

    const int ZB = 2048, ZT = 256;

    // ---- layer 0 ----
    zero4_kernel<<<64, ZT>>>((float4*)cnt, (size_t)n / 4);
    zero4_kernel<<<ZB, ZT>>>((float4*)agg, (size_t)n * 7 / 4);
    zero4_kernel<<<16, ZT>>>((float4*)pooled, (size_t)GRAPHS * 256 / 4);
    scatter7_kernel<<<(E + 255) / 256, 256>>>(x, ei, E, n);
    invc_kernel<<<(n + 255) / 256, 256>>>(n);
    gemm0_kernel<<<n, 128>>>(x, Wl0, bl0, Wr0, g0, be0, rm0, rv0, n);

    // ---- layer 1 ----
    zero4_kernel<<<ZB, ZT>>>((float4*)agg, (size_t)n * 32);
    scatter128_kernel<<<(int)(((long long)E * 32 + 255) / 256), 256>>>(h1, ei, E, n);
    gemm_sage_kernel<128><<<dim3((n + 127) / 128, 1), 256>>>(
        h1, Wl1, Wr1, bl1, g1, be1, rm1, rv1, h2, n);

    // ---- layer 2 (writes x-output directly into d_out) ----
    zero4_kernel<<<ZB, ZT>>>((float4*)agg, (size_t)n * 32);
    scatter128_kernel<<<(int)(((long long)E * 32 + 255) / 256), 256>>>(h2, ei, E, n);
    gemm_sage_kernel<256><<<dim3((n + 127) / 128, 2), 256>>>(
        h2, Wl2, Wr2, bl2, g2, be2, rm2, rv2, xout, n);

    // ---- global add pool ----
    pool_kernel<<<(n + POOL_ROWS - 1) / POOL_ROWS, 256>>>(xout, batch, pooled, n);
}

// round 12
// speedup vs baseline: 1.4155x; 1.4155x over previous
#include <cuda_runtime.h>
#include <cstdint>
#include <cstddef>

#define NODES_MAX 100000
#define GRAPHS 64
#define EPS 1e-5f

// -------- scratch (static __device__ arrays; no allocation allowed) --------
__device__ float d_agg[(size_t)NODES_MAX * 128];
__device__ float d_h1 [(size_t)NODES_MAX * 128];
__device__ float d_h2 [(size_t)NODES_MAX * 128];
__device__ float d_invc[NODES_MAX];

// ---------------------------------------------------------------------------
// vectorized global reductions (sm_90+)
// ---------------------------------------------------------------------------
__device__ __forceinline__ void red_v4(float* a, float x, float y, float z, float w) {
    asm volatile("red.global.add.v4.f32 [%0], {%1, %2, %3, %4};"
                 :: "l"(a), "f"(x), "f"(y), "f"(z), "f"(w) : "memory");
}

// ---------------------------------------------------------------------------
// zero-fill (float4 granularity)
// ---------------------------------------------------------------------------
__global__ void zero4_kernel(float4* __restrict__ p, size_t n4) {
    size_t i = (size_t)blockIdx.x * blockDim.x + threadIdx.x;
    size_t stride = (size_t)gridDim.x * blockDim.x;
    float4 z = make_float4(0.f, 0.f, 0.f, 0.f);
    for (; i < n4; i += stride) p[i] = z;
}

// ---------------------------------------------------------------------------
// Layer-0 edge scatter into stride-8 padded agg rows; count folded into
// slot 7. One thread per edge, 2 vector REDs per edge.
// ---------------------------------------------------------------------------
__global__ void scatter7_kernel(const float* __restrict__ x,
                                const int* __restrict__ ei, int E, int n) {
    int e = blockIdx.x * blockDim.x + threadIdx.x;
    if (e >= E) return;
    int s = ei[e];
    int d = ei[(size_t)E + e];
    if ((unsigned)s >= (unsigned)n || (unsigned)d >= (unsigned)n) return;
    const float* xr = x + (size_t)s * 7;
    float x0 = __ldg(xr + 0), x1 = __ldg(xr + 1), x2 = __ldg(xr + 2), x3 = __ldg(xr + 3);
    float x4 = __ldg(xr + 4), x5 = __ldg(xr + 5), x6 = __ldg(xr + 6);
    float* a = d_agg + (size_t)d * 8;
    red_v4(a,     x0, x1, x2, x3);
    red_v4(a + 4, x4, x5, x6, 1.0f);   // slot 7 = degree count
}

// ---------------------------------------------------------------------------
// din=128 edge scatter: one warp per edge; lane does one 16B gather + one
// 128-bit vector RED.
// ---------------------------------------------------------------------------
__global__ void scatter128_kernel(const float* __restrict__ feat,
                                  const int* __restrict__ ei, int E, int n) {
    int idx = blockIdx.x * blockDim.x + threadIdx.x;
    int e = idx >> 5;
    int lane = idx & 31;
    if (e >= E) return;
    int s = ei[e];
    int d = ei[(size_t)E + e];
    if ((unsigned)s >= (unsigned)n || (unsigned)d >= (unsigned)n) return;
    float4 v = reinterpret_cast<const float4*>(feat + (size_t)s * 128)[lane];
    red_v4(d_agg + (size_t)d * 128 + lane * 4, v.x, v.y, v.z, v.w);
}

// ---------------------------------------------------------------------------
// invc[i] = 1 / max(cnt[i], 1)  (cnt lives in agg slot 7 for layer 0)
// ---------------------------------------------------------------------------
__global__ void invc_kernel(int n) {
    int i = blockIdx.x * blockDim.x + threadIdx.x;
    if (i < n) d_invc[i] = 1.0f / fmaxf(d_agg[(size_t)i * 8 + 7], 1.0f);
}

// ---------------------------------------------------------------------------
// Layer 0: din=7 -> dout=128. 32 nodes per block; weights staged in smem.
// ---------------------------------------------------------------------------
#define G0_NODES 32
__global__ void __launch_bounds__(128)
gemm0_kernel(const float* __restrict__ x,
             const float* __restrict__ Wl, const float* __restrict__ bl,
             const float* __restrict__ Wr,
             const float* __restrict__ g,  const float* __restrict__ be,
             const float* __restrict__ rm, const float* __restrict__ rv,
             int n) {
    __shared__ float sW0[7][128];
    __shared__ float sW1[7][128];
    __shared__ float sx[G0_NODES][8];
    __shared__ float sm[G0_NODES][8];
    int tid = threadIdx.x;       // 0..127
    int node0 = blockIdx.x * G0_NODES;

#pragma unroll
    for (int k = 0; k < 7; k++) {
        sW0[k][tid] = Wl[k * 128 + tid];
        sW1[k][tid] = Wr[k * 128 + tid];
    }
    for (int i = tid; i < G0_NODES * 7; i += 128) {
        int ni = i / 7, k = i % 7;
        int node = node0 + ni;
        float xv = 0.f, mv = 0.f;
        if (node < n) {
            xv = x[(size_t)node * 7 + k];
            mv = d_agg[(size_t)node * 8 + k] * d_invc[node];
        }
        sx[ni][k] = xv;
        sm[ni][k] = mv;
    }
    __syncthreads();

    int j = tid;
    float s = g[j] * rsqrtf(rv[j] + EPS);
    float t = be[j] + (bl[j] - rm[j]) * s;
#pragma unroll 4
    for (int ni = 0; ni < G0_NODES; ni++) {
        int node = node0 + ni;
        if (node >= n) break;
        float acc = 0.f;
#pragma unroll
        for (int k = 0; k < 7; k++)
            acc += sx[ni][k] * sW0[k][j] + sm[ni][k] * sW1[k][j];
        d_h1[(size_t)node * 128 + j] = fmaxf(acc * s + t, 0.0f);
    }
}

// ---------------------------------------------------------------------------
// Main SGEMM for layers 1/2 (din=128).
//   C = relu(BN(A@Wl + bl + (agg*invc)@Wr))
// BM=128, BN=128, BK=16, 256 threads, 8x8 register tiles, double-buffered
// smem with one __syncthreads per tile; LDG of tile t+1 overlaps compute
// of tile t. 16 logical tiles = 2 operand phases x 8 K-chunks.
// ---------------------------------------------------------------------------
template <int DOUT>
__global__ void __launch_bounds__(256, 2)
gemm_sage_kernel(const float* __restrict__ A,
                 const float* __restrict__ Wl, const float* __restrict__ Wr,
                 const float* __restrict__ bl,
                 const float* __restrict__ g,  const float* __restrict__ be,
                 const float* __restrict__ rm, const float* __restrict__ rv,
                 float* __restrict__ C, int n) {
    const int BM = 128, BN = 128, BK = 16;
    __shared__ __align__(16) float As[2][BK][136];
    __shared__ __align__(16) float Bs[2][BK][BN];
    __shared__ float sInv[BM];

    int tid  = threadIdx.x;
    int row0 = blockIdx.x * BM;
    int col0 = blockIdx.y * BN;

    if (tid < BM) {
        int r = row0 + tid;
        sInv[tid] = (r < n) ? d_invc[r] : 0.0f;
    }
    __syncthreads();

    // A loader: thread -> (row, k-octet)
    int aRow = tid >> 1;            // 0..127
    int aK   = (tid & 1) << 3;      // 0 or 8
    // B loader: thread -> (k-row, col-octet)
    int bK   = tid >> 4;            // 0..15
    int bJ   = (tid & 15) << 3;     // 0..120
    // compute mapping
    int tm0 = (tid >> 4) << 3;
    int tn0 = (tid & 15) << 3;

    int arow_g  = row0 + aRow;
    bool aValid = arow_g < n;
    float scA   = sInv[aRow];

    const float* aggP = d_agg;
    const int NT = 16;              // 2 phases x 8 chunks

    float4 va0, va1, vb0, vb1;
    auto ldg_tile = [&](int t) {
        int p  = t >> 3;
        int kk = t & 7;
        const float* __restrict__ P = p ? aggP : A;
        const float* __restrict__ W = p ? Wr : Wl;
        va0 = make_float4(0.f, 0.f, 0.f, 0.f);
        va1 = va0;
        if (aValid) {
            const float* src = P + (size_t)arow_g * 128 + kk * BK + aK;
            va0 = *reinterpret_cast<const float4*>(src);
            va1 = *reinterpret_cast<const float4*>(src + 4);
        }
        if (p) {
            va0.x *= scA; va0.y *= scA; va0.z *= scA; va0.w *= scA;
            va1.x *= scA; va1.y *= scA; va1.z *= scA; va1.w *= scA;
        }
        const float* wsrc = W + (size_t)(kk * BK + bK) * DOUT + col0 + bJ;
        vb0 = *reinterpret_cast<const float4*>(wsrc);
        vb1 = *reinterpret_cast<const float4*>(wsrc + 4);
    };
    auto sts_tile = [&](int buf) {
        As[buf][aK + 0][aRow] = va0.x;
        As[buf][aK + 1][aRow] = va0.y;
        As[buf][aK + 2][aRow] = va0.z;
        As[buf][aK + 3][aRow] = va0.w;
        As[buf][aK + 4][aRow] = va1.x;
        As[buf][aK + 5][aRow] = va1.y;
        As[buf][aK + 6][aRow] = va1.z;
        As[buf][aK + 7][aRow] = va1.w;
        *reinterpret_cast<float4*>(&Bs[buf][bK][bJ])     = vb0;
        *reinterpret_cast<float4*>(&Bs[buf][bK][bJ + 4]) = vb1;
    };

    float acc[8][8];
#pragma unroll
    for (int i = 0; i < 8; i++)
#pragma unroll
        for (int j = 0; j < 8; j++) acc[i][j] = 0.0f;

    ldg_tile(0);
    sts_tile(0);
    __syncthreads();

#pragma unroll 1
    for (int t = 0; t < NT; ++t) {
        int cur = t & 1;
        if (t + 1 < NT) ldg_tile(t + 1);       // LDG overlaps compute below
#pragma unroll
        for (int k = 0; k < BK; k++) {
            float a[8], b[8];
            *(float4*)&a[0] = *(const float4*)&As[cur][k][tm0];
            *(float4*)&a[4] = *(const float4*)&As[cur][k][tm0 + 4];
            *(float4*)&b[0] = *(const float4*)&Bs[cur][k][tn0];
            *(float4*)&b[4] = *(const float4*)&Bs[cur][k][tn0 + 4];
#pragma unroll
            for (int i = 0; i < 8; i++)
#pragma unroll
                for (int j = 0; j < 8; j++) acc[i][j] += a[i] * b[j];
        }
        if (t + 1 < NT) sts_tile(1 - cur);     // safe: buf 1-cur last read at t-1
        __syncthreads();
    }

    // ---- epilogue: fold bias + eval-mode BN + ReLU ----
    float sj[8], tj[8];
#pragma unroll
    for (int j = 0; j < 8; j++) {
        int col = col0 + tn0 + j;
        float s = g[col] * rsqrtf(rv[col] + EPS);
        sj[j] = s;
        tj[j] = be[col] + (bl[col] - rm[col]) * s;
    }
#pragma unroll
    for (int i = 0; i < 8; i++) {
        int r = row0 + tm0 + i;
        if (r < n) {
            float* crow = C + (size_t)r * DOUT + col0 + tn0;
#pragma unroll
            for (int j = 0; j < 8; j++)
                crow[j] = fmaxf(acc[i][j] * sj[j] + tj[j], 0.0f);
        }
    }
}

// ---------------------------------------------------------------------------
// global_add_pool: batch is SORTED; each thread owns one feature column,
// walks a row-chunk accumulating in a register, flushes on graph boundary.
// ---------------------------------------------------------------------------
#define POOL_ROWS 512
__global__ void pool_kernel(const float* __restrict__ xf,
                            const int* __restrict__ batch,
                            float* __restrict__ pooled, int n) {
    int j  = threadIdx.x;                 // 0..255 feature column
    int r0 = blockIdx.x * POOL_ROWS;
    if (r0 >= n) return;
    int r1 = min(r0 + POOL_ROWS, n);
    int cur = batch[r0];
    float acc = 0.0f;
    for (int r = r0; r < r1; ++r) {
        int b = batch[r];                 // uniform across block -> broadcast
        if (b != cur) {
            if ((unsigned)cur < GRAPHS) atomicAdd(&pooled[cur * 256 + j], acc);
            acc = 0.0f;
            cur = b;
        }
        acc += xf[(size_t)r * 256 + j];
    }
    if ((unsigned)cur < GRAPHS) atomicAdd(&pooled[cur * 256 + j], acc);
}

// ---------------------------------------------------------------------------
// launch
// ---------------------------------------------------------------------------
extern "C" void kernel_launch(void* const* d_in, const int* in_sizes, int n_in,
                              void* d_out, int out_size) {
    const float* x     = (const float*)d_in[0];
    const int*   ei    = (const int*)d_in[1];
    const int*   batch = (const int*)d_in[2];

    const float* Wl0 = (const float*)d_in[3];
    const float* bl0 = (const float*)d_in[4];
    const float* Wr0 = (const float*)d_in[5];
    const float* g0  = (const float*)d_in[6];
    const float* be0 = (const float*)d_in[7];
    const float* rm0 = (const float*)d_in[8];
    const float* rv0 = (const float*)d_in[9];

    const float* Wl1 = (const float*)d_in[10];
    const float* bl1 = (const float*)d_in[11];
    const float* Wr1 = (const float*)d_in[12];
    const float* g1  = (const float*)d_in[13];
    const float* be1 = (const float*)d_in[14];
    const float* rm1 = (const float*)d_in[15];
    const float* rv1 = (const float*)d_in[16];

    const float* Wl2 = (const float*)d_in[17];
    const float* bl2 = (const float*)d_in[18];
    const float* Wr2 = (const float*)d_in[19];
    const float* g2  = (const float*)d_in[20];
    const float* be2 = (const float*)d_in[21];
    const float* rm2 = (const float*)d_in[22];
    const float* rv2 = (const float*)d_in[23];

    const int E = in_sizes[1] / 2;
    const int n = in_sizes[2];

    float* out    = (float*)d_out;
    float* pooled = out;                        // [64, 256]
    float* xout   = out + (size_t)GRAPHS * 256; // [n, 256]

    float *agg = nullptr, *h1 = nullptr, *h2 = nullptr;
    cudaGetSymbolAddress((void**)&agg, d_agg);
    cudaGetSymbolAddress((void**)&h1,  d_h1);
    cudaGetSymbolAddress((void**)&h2,  d_h2);

    const int ZB = 2048, ZT = 256;

    // ---- layer 0 (agg rows stride 8, cnt in slot 7) ----
    zero4_kernel<<<ZB, ZT>>>((float4*)agg, (size_t)n * 2);
    zero4_kernel<<<16, ZT>>>((float4*)pooled, (size_t)GRAPHS * 64);
    scatter7_kernel<<<(E + 255) / 256, 256>>>(x, ei, E, n);
    invc_kernel<<<(n + 255) / 256, 256>>>(n);
    gemm0_kernel<<<(n + G0_NODES - 1) / G0_NODES, 128>>>(
        x, Wl0, bl0, Wr0, g0, be0, rm0, rv0, n);

    // ---- layer 1 ----
    zero4_kernel<<<ZB, ZT>>>((float4*)agg, (size_t)n * 32);
    scatter128_kernel<<<(int)(((long long)E * 32 + 255) / 256), 256>>>(h1, ei, E, n);
    gemm_sage_kernel<128><<<dim3((n + 127) / 128, 1), 256>>>(
        h1, Wl1, Wr1, bl1, g1, be1, rm1, rv1, h2, n);

    // ---- layer 2 (writes x-output directly into d_out) ----
    zero4_kernel<<<ZB, ZT>>>((float4*)agg, (size_t)n * 32);
    scatter128_kernel<<<(int)(((long long)E * 32 + 255) / 256), 256>>>(h2, ei, E, n);
    gemm_sage_kernel<256><<<dim3((n + 127) / 128, 2), 256>>>(
        h2, Wl2, Wr2, bl2, g2, be2, rm2, rv2, xout, n);

    // ---- global add pool ----
    pool_kernel<<<(n + POOL_ROWS - 1) / POOL_ROWS, 256>>>(xout, batch, pooled, n);
}

// round 16
// speedup vs baseline: 2.0302x; 1.4343x over previous
#include <cuda_runtime.h>
#include <cuda_bf16.h>
#include <cstdint>
#include <cstddef>

#define NODES_MAX 100000
#define GRAPHS 64
#define EPS 1e-5f

// -------- scratch (static __device__ arrays; no allocation allowed) --------
__device__ float d_agg[(size_t)NODES_MAX * 128];
__device__ float d_h1 [(size_t)NODES_MAX * 128];
__device__ float d_h2 [(size_t)NODES_MAX * 128];
__device__ float d_invc[NODES_MAX];
// pre-split weights, stacked [Wl;Wr] along K: Wb[n][k], k in [0,256) (k contiguous
// per n == column-major KxN, exactly what mma .row.col wants for B)
__device__ __nv_bfloat16 d_w1hi[128 * 256];
__device__ __nv_bfloat16 d_w1lo[128 * 256];
__device__ __nv_bfloat16 d_w2hi[256 * 256];
__device__ __nv_bfloat16 d_w2lo[256 * 256];

// ---------------------------------------------------------------------------
// baseline-PTX helpers (all valid on compute_103: sm_75+/80+ features only)
// ---------------------------------------------------------------------------
__device__ __forceinline__ uint32_t smem_to_u32(const void* p) {
    uint32_t a;
    asm("{ .reg .u64 t; cvta.to.shared.u64 t, %1; cvt.u32.u64 %0, t; }"
        : "=r"(a) : "l"(p));
    return a;
}
__device__ __forceinline__ void ldsm_x4(uint32_t* r, uint32_t addr) {
    asm volatile("ldmatrix.sync.aligned.m8n8.x4.shared.b16 {%0,%1,%2,%3}, [%4];"
                 : "=r"(r[0]), "=r"(r[1]), "=r"(r[2]), "=r"(r[3]) : "r"(addr));
}
__device__ __forceinline__ void ldsm_x2(uint32_t* r, uint32_t addr) {
    asm volatile("ldmatrix.sync.aligned.m8n8.x2.shared.b16 {%0,%1}, [%2];"
                 : "=r"(r[0]), "=r"(r[1]) : "r"(addr));
}
__device__ __forceinline__ void mma_bf16(float* c, const uint32_t* a, const uint32_t* b) {
    asm volatile("mma.sync.aligned.m16n8k16.row.col.f32.bf16.bf16.f32 "
                 "{%0,%1,%2,%3}, {%4,%5,%6,%7}, {%8,%9}, {%0,%1,%2,%3};"
                 : "+f"(c[0]), "+f"(c[1]), "+f"(c[2]), "+f"(c[3])
                 : "r"(a[0]), "r"(a[1]), "r"(a[2]), "r"(a[3]), "r"(b[0]), "r"(b[1]));
}
__device__ __forceinline__ void red_v4(float* a, float x, float y, float z, float w) {
    asm volatile("red.global.add.v4.f32 [%0], {%1, %2, %3, %4};"
                 :: "l"(a), "f"(x), "f"(y), "f"(z), "f"(w) : "memory");
}

// ---------------------------------------------------------------------------
// zero-fill
// ---------------------------------------------------------------------------
__global__ void zero4_kernel(float4* __restrict__ p, size_t n4) {
    size_t i = (size_t)blockIdx.x * blockDim.x + threadIdx.x;
    size_t stride = (size_t)gridDim.x * blockDim.x;
    float4 z = make_float4(0.f, 0.f, 0.f, 0.f);
    for (; i < n4; i += stride) p[i] = z;
}

// ---------------------------------------------------------------------------
// weight prep: Wb[n][k] = (k<128 ? Wl[k][n] : Wr[k-128][n]) split into bf16 hi/lo
// ---------------------------------------------------------------------------
__global__ void prep_w_kernel(const float* __restrict__ Wl, const float* __restrict__ Wr,
                              __nv_bfloat16* __restrict__ hi, __nv_bfloat16* __restrict__ lo,
                              int dout) {
    int idx = blockIdx.x * blockDim.x + threadIdx.x;
    if (idx >= dout * 256) return;
    int nn = idx >> 8, k = idx & 255;
    float w = (k < 128) ? Wl[k * dout + nn] : Wr[(k - 128) * dout + nn];
    __nv_bfloat16 h = __float2bfloat16(w);
    hi[idx] = h;
    lo[idx] = __float2bfloat16(w - __bfloat162float(h));
}

// ---------------------------------------------------------------------------
// Layer-0 edge scatter (stride-8 agg rows, count in slot 7)
// ---------------------------------------------------------------------------
__global__ void scatter7_kernel(const float* __restrict__ x,
                                const int* __restrict__ ei, int E, int n) {
    int e = blockIdx.x * blockDim.x + threadIdx.x;
    if (e >= E) return;
    int s = ei[e];
    int d = ei[(size_t)E + e];
    if ((unsigned)s >= (unsigned)n || (unsigned)d >= (unsigned)n) return;
    const float* xr = x + (size_t)s * 7;
    float x0 = __ldg(xr + 0), x1 = __ldg(xr + 1), x2 = __ldg(xr + 2), x3 = __ldg(xr + 3);
    float x4 = __ldg(xr + 4), x5 = __ldg(xr + 5), x6 = __ldg(xr + 6);
    float* a = d_agg + (size_t)d * 8;
    red_v4(a,     x0, x1, x2, x3);
    red_v4(a + 4, x4, x5, x6, 1.0f);
}

// ---------------------------------------------------------------------------
// din=128 edge scatter: warp/edge, one v4 RED per lane
// ---------------------------------------------------------------------------
__global__ void scatter128_kernel(const float* __restrict__ feat,
                                  const int* __restrict__ ei, int E, int n) {
    int idx = blockIdx.x * blockDim.x + threadIdx.x;
    int e = idx >> 5;
    int lane = idx & 31;
    if (e >= E) return;
    int s = ei[e];
    int d = ei[(size_t)E + e];
    if ((unsigned)s >= (unsigned)n || (unsigned)d >= (unsigned)n) return;
    float4 v = reinterpret_cast<const float4*>(feat + (size_t)s * 128)[lane];
    red_v4(d_agg + (size_t)d * 128 + lane * 4, v.x, v.y, v.z, v.w);
}

__global__ void invc_kernel(int n) {
    int i = blockIdx.x * blockDim.x + threadIdx.x;
    if (i < n) d_invc[i] = 1.0f / fmaxf(d_agg[(size_t)i * 8 + 7], 1.0f);
}

// ---------------------------------------------------------------------------
// Layer 0: din=7 -> dout=128. 32 nodes/block; weights staged in smem.
// ---------------------------------------------------------------------------
#define G0_NODES 32
__global__ void __launch_bounds__(128)
gemm0_kernel(const float* __restrict__ x,
             const float* __restrict__ Wl, const float* __restrict__ bl,
             const float* __restrict__ Wr,
             const float* __restrict__ g,  const float* __restrict__ be,
             const float* __restrict__ rm, const float* __restrict__ rv,
             int n) {
    __shared__ float sW0[7][128];
    __shared__ float sW1[7][128];
    __shared__ float sx[G0_NODES][8];
    __shared__ float sm[G0_NODES][8];
    int tid = threadIdx.x;
    int node0 = blockIdx.x * G0_NODES;
#pragma unroll
    for (int k = 0; k < 7; k++) {
        sW0[k][tid] = Wl[k * 128 + tid];
        sW1[k][tid] = Wr[k * 128 + tid];
    }
    for (int i = tid; i < G0_NODES * 7; i += 128) {
        int ni = i / 7, k = i % 7;
        int node = node0 + ni;
        float xv = 0.f, mv = 0.f;
        if (node < n) {
            xv = x[(size_t)node * 7 + k];
            mv = d_agg[(size_t)node * 8 + k] * d_invc[node];
        }
        sx[ni][k] = xv;
        sm[ni][k] = mv;
    }
    __syncthreads();
    int j = tid;
    float s = g[j] * rsqrtf(rv[j] + EPS);
    float t = be[j] + (bl[j] - rm[j]) * s;
#pragma unroll 4
    for (int ni = 0; ni < G0_NODES; ni++) {
        int node = node0 + ni;
        if (node >= n) break;
        float acc = 0.f;
#pragma unroll
        for (int k = 0; k < 7; k++)
            acc += sx[ni][k] * sW0[k][j] + sm[ni][k] * sW1[k][j];
        d_h1[(size_t)node * 128 + j] = fmaxf(acc * s + t, 0.0f);
    }
}

// ---------------------------------------------------------------------------
// bf16 split-precision GEMM via mma.sync (HMMA fallback pipe, layers 1/2).
//   C[m][col0+j] = relu(BN( sum_k Afull[m][k] * Wb[col0+j][k] ))
// Afull = [h | agg*invc], K=256 in 8 chunks of 32.
// D += Ah*Bh + Ah*Bl + Al*Bh  (fp32 accumulators; Al*Bl dropped, ~2^-16 rel).
// Tile 128x128, 8 warps (2m x 4n), warp tile 64x32 of m16n8k16 fragments.
// smem rows stride 40 bf16 (80 B): 16B-aligned, conflict-free ldmatrix.
// ---------------------------------------------------------------------------
#define AST 40

template <int DOUT>
__global__ void __launch_bounds__(256)
gemm_mma_kernel(const float* __restrict__ A,
                const __nv_bfloat16* __restrict__ WbHi,
                const __nv_bfloat16* __restrict__ WbLo,
                const float* __restrict__ bl,
                const float* __restrict__ g,  const float* __restrict__ be,
                const float* __restrict__ rm, const float* __restrict__ rv,
                float* __restrict__ C, int n) {
    __shared__ __align__(16) __nv_bfloat16 sAh[128 * AST];
    __shared__ __align__(16) __nv_bfloat16 sAl[128 * AST];
    __shared__ __align__(16) __nv_bfloat16 sBh[128 * AST];
    __shared__ __align__(16) __nv_bfloat16 sBl[128 * AST];
    __shared__ float sInv[128], sS[128], sT[128];

    int tid  = threadIdx.x;
    int lane = tid & 31;
    int wid  = tid >> 5;
    int row0 = blockIdx.x * 128;
    int col0 = blockIdx.y * 128;
    int wm = wid & 1;          // 0..1 -> 64 M-rows
    int wn = wid >> 1;         // 0..3 -> 32 N-cols

    if (tid < 128) {
        int r = row0 + tid;
        sInv[tid] = (r < n) ? d_invc[r] : 0.0f;
        int col = col0 + tid;
        float s = g[col] * rsqrtf(rv[col] + EPS);
        sS[tid] = s;
        sT[tid] = be[col] + (bl[col] - rm[col]) * s;
    }
    __syncthreads();

    uint32_t uAh = smem_to_u32(sAh), uAl = smem_to_u32(sAl);
    uint32_t uBh = smem_to_u32(sBh), uBl = smem_to_u32(sBl);

    float acc[4][4][4];
#pragma unroll
    for (int mt = 0; mt < 4; mt++)
#pragma unroll
        for (int nt = 0; nt < 4; nt++)
#pragma unroll
            for (int q = 0; q < 4; q++) acc[mt][nt][q] = 0.f;

    // ldmatrix lane address components (constant across chunks)
    int ra = (lane & 7) + ((lane >> 3) & 1) * 8;   // A: row within 16
    int kaH = ((lane >> 4) & 1) * 8;               // A: k-half select
    int rb = lane & 7;                             // B: n within 8
    int kbH = ((lane >> 3) & 1) * 8;               // B: k-half select

#pragma unroll 1
    for (int c = 0; c < 8; ++c) {
        __syncthreads();
        // ---- stage A chunk [128 rows x 32 k] f32 -> bf16 hi/lo ----
#pragma unroll
        for (int it = 0; it < 4; ++it) {
            int q   = tid + it * 256;       // 0..1023
            int row = q >> 3;
            int k4  = (q & 7) * 4;
            int rg  = row0 + row;
            float4 f = make_float4(0.f, 0.f, 0.f, 0.f);
            if (rg < n) {
                const float* src = (c < 4)
                    ? A     + (size_t)rg * 128 +  c      * 32 + k4
                    : d_agg + (size_t)rg * 128 + (c - 4) * 32 + k4;
                f = *(const float4*)src;
                if (c >= 4) { float sc = sInv[row]; f.x *= sc; f.y *= sc; f.z *= sc; f.w *= sc; }
            }
            __nv_bfloat162 h0 = __float22bfloat162_rn(make_float2(f.x, f.y));
            __nv_bfloat162 h1 = __float22bfloat162_rn(make_float2(f.z, f.w));
            float2 hf0 = __bfloat1622float2(h0);
            float2 hf1 = __bfloat1622float2(h1);
            __nv_bfloat162 l0 = __float22bfloat162_rn(make_float2(f.x - hf0.x, f.y - hf0.y));
            __nv_bfloat162 l1 = __float22bfloat162_rn(make_float2(f.z - hf1.x, f.w - hf1.y));
            uint32_t off = row * AST + k4;                 // bf16 units, 8B-aligned
            *(uint2*)(sAh + off) = make_uint2(*(uint32_t*)&h0, *(uint32_t*)&h1);
            *(uint2*)(sAl + off) = make_uint2(*(uint32_t*)&l0, *(uint32_t*)&l1);
        }
        // ---- stage B chunk [128 n x 32 k] (pre-split bf16 in gmem) ----
#pragma unroll
        for (int it = 0; it < 2; ++it) {
            int q  = tid + it * 256;        // 0..511
            int nl = q >> 2;
            int k8 = (q & 3) * 8;
            size_t src = (size_t)(col0 + nl) * 256 + c * 32 + k8;
            uint4 h = *(const uint4*)(WbHi + src);
            uint4 l = *(const uint4*)(WbLo + src);
            uint32_t off = nl * AST + k8;                  // 16B-aligned
            *(uint4*)(sBh + off) = h;
            *(uint4*)(sBl + off) = l;
        }
        __syncthreads();
        // ---- compute: 2 K=16 steps x (4m x 4n) fragments x 3 split terms ----
#pragma unroll
        for (int ks = 0; ks < 32; ks += 16) {
            uint32_t ah[4][4], al[4][4], bh[4][2], blo[4][2];
#pragma unroll
            for (int mt = 0; mt < 4; ++mt) {
                uint32_t off = ((wm * 64 + mt * 16 + ra) * AST + ks + kaH) * 2;
                ldsm_x4(ah[mt], uAh + off);
                ldsm_x4(al[mt], uAl + off);
            }
#pragma unroll
            for (int nt = 0; nt < 4; ++nt) {
                uint32_t off = ((wn * 32 + nt * 8 + rb) * AST + ks + kbH) * 2;
                ldsm_x2(bh[nt],  uBh + off);
                ldsm_x2(blo[nt], uBl + off);
            }
#pragma unroll
            for (int mt = 0; mt < 4; ++mt)
#pragma unroll
                for (int nt = 0; nt < 4; ++nt) {
                    mma_bf16(acc[mt][nt], ah[mt], bh[nt]);
                    mma_bf16(acc[mt][nt], ah[mt], blo[nt]);
                    mma_bf16(acc[mt][nt], al[mt], bh[nt]);
                }
        }
    }

    // ---- epilogue: BN + ReLU fused on fragments ----
#pragma unroll
    for (int mt = 0; mt < 4; ++mt) {
        int rbase = row0 + wm * 64 + mt * 16 + (lane >> 2);
#pragma unroll
        for (int nt = 0; nt < 4; ++nt) {
            int cl = wn * 32 + nt * 8 + 2 * (lane & 3);
            float s0 = sS[cl], s1 = sS[cl + 1];
            float t0 = sT[cl], t1 = sT[cl + 1];
            if (rbase < n) {
                float2 o = make_float2(fmaxf(acc[mt][nt][0] * s0 + t0, 0.f),
                                       fmaxf(acc[mt][nt][1] * s1 + t1, 0.f));
                *(float2*)(C + (size_t)rbase * DOUT + col0 + cl) = o;
            }
            if (rbase + 8 < n) {
                float2 o = make_float2(fmaxf(acc[mt][nt][2] * s0 + t0, 0.f),
                                       fmaxf(acc[mt][nt][3] * s1 + t1, 0.f));
                *(float2*)(C + (size_t)(rbase + 8) * DOUT + col0 + cl) = o;
            }
        }
    }
}

// ---------------------------------------------------------------------------
// global_add_pool (batch sorted)
// ---------------------------------------------------------------------------
#define POOL_ROWS 512
__global__ void pool_kernel(const float* __restrict__ xf,
                            const int* __restrict__ batch,
                            float* __restrict__ pooled, int n) {
    int j  = threadIdx.x;
    int r0 = blockIdx.x * POOL_ROWS;
    if (r0 >= n) return;
    int r1 = min(r0 + POOL_ROWS, n);
    int cur = batch[r0];
    float acc = 0.0f;
    for (int r = r0; r < r1; ++r) {
        int b = batch[r];
        if (b != cur) {
            if ((unsigned)cur < GRAPHS) atomicAdd(&pooled[cur * 256 + j], acc);
            acc = 0.0f;
            cur = b;
        }
        acc += xf[(size_t)r * 256 + j];
    }
    if ((unsigned)cur < GRAPHS) atomicAdd(&pooled[cur * 256 + j], acc);
}

// ---------------------------------------------------------------------------
// launch
// ---------------------------------------------------------------------------
extern "C" void kernel_launch(void* const* d_in, const int* in_sizes, int n_in,
                              void* d_out, int out_size) {
    const float* x     = (const float*)d_in[0];
    const int*   ei    = (const int*)d_in[1];
    const int*   batch = (const int*)d_in[2];

    const float* Wl0 = (const float*)d_in[3];
    const float* bl0 = (const float*)d_in[4];
    const float* Wr0 = (const float*)d_in[5];
    const float* g0  = (const float*)d_in[6];
    const float* be0 = (const float*)d_in[7];
    const float* rm0 = (const float*)d_in[8];
    const float* rv0 = (const float*)d_in[9];

    const float* Wl1 = (const float*)d_in[10];
    const float* bl1 = (const float*)d_in[11];
    const float* Wr1 = (const float*)d_in[12];
    const float* g1  = (const float*)d_in[13];
    const float* be1 = (const float*)d_in[14];
    const float* rm1 = (const float*)d_in[15];
    const float* rv1 = (const float*)d_in[16];

    const float* Wl2 = (const float*)d_in[17];
    const float* bl2 = (const float*)d_in[18];
    const float* Wr2 = (const float*)d_in[19];
    const float* g2  = (const float*)d_in[20];
    const float* be2 = (const float*)d_in[21];
    const float* rm2 = (const float*)d_in[22];
    const float* rv2 = (const float*)d_in[23];

    const int E = in_sizes[1] / 2;
    const int n = in_sizes[2];

    float* out    = (float*)d_out;
    float* pooled = out;                        // [64, 256]
    float* xout   = out + (size_t)GRAPHS * 256; // [n, 256]

    float *agg = nullptr, *h1 = nullptr, *h2 = nullptr;
    cudaGetSymbolAddress((void**)&agg, d_agg);
    cudaGetSymbolAddress((void**)&h1,  d_h1);
    cudaGetSymbolAddress((void**)&h2,  d_h2);
    __nv_bfloat16 *w1h, *w1l, *w2h, *w2l;
    cudaGetSymbolAddress((void**)&w1h, d_w1hi);
    cudaGetSymbolAddress((void**)&w1l, d_w1lo);
    cudaGetSymbolAddress((void**)&w2h, d_w2hi);
    cudaGetSymbolAddress((void**)&w2l, d_w2lo);

    const int ZB = 2048, ZT = 256;
    int mtiles = (n + 127) / 128;

    // ---- weight prep (tiny) ----
    prep_w_kernel<<<(128 * 256 + 255) / 256, 256>>>(Wl1, Wr1, w1h, w1l, 128);
    prep_w_kernel<<<(256 * 256 + 255) / 256, 256>>>(Wl2, Wr2, w2h, w2l, 256);

    // ---- layer 0 (agg rows stride 8, cnt in slot 7) ----
    zero4_kernel<<<ZB, ZT>>>((float4*)agg, (size_t)n * 2);
    zero4_kernel<<<16, ZT>>>((float4*)pooled, (size_t)GRAPHS * 64);
    scatter7_kernel<<<(E + 255) / 256, 256>>>(x, ei, E, n);
    invc_kernel<<<(n + 255) / 256, 256>>>(n);
    gemm0_kernel<<<(n + G0_NODES - 1) / G0_NODES, 128>>>(
        x, Wl0, bl0, Wr0, g0, be0, rm0, rv0, n);

    // ---- layer 1 ----
    zero4_kernel<<<ZB, ZT>>>((float4*)agg, (size_t)n * 32);
    scatter128_kernel<<<(int)(((long long)E * 32 + 255) / 256), 256>>>(h1, ei, E, n);
    gemm_mma_kernel<128><<<dim3(mtiles, 1), 256>>>(
        h1, w1h, w1l, bl1, g1, be1, rm1, rv1, h2, n);

    // ---- layer 2 (writes x-output directly into d_out) ----
    zero4_kernel<<<ZB, ZT>>>((float4*)agg, (size_t)n * 32);
    scatter128_kernel<<<(int)(((long long)E * 32 + 255) / 256), 256>>>(h2, ei, E, n);
    gemm_mma_kernel<256><<<dim3(mtiles, 2), 256>>>(
        h2, w2h, w2l, bl2, g2, be2, rm2, rv2, xout, n);

    // ---- global add pool ----
    pool_kernel<<<(n + POOL_ROWS - 1) / POOL_ROWS, 256>>>(xout, batch, pooled, n);
}

// round 17
// speedup vs baseline: 2.6860x; 1.3230x over previous
#include <cuda_runtime.h>
#include <cuda_bf16.h>
#include <cstdint>
#include <cstddef>

#define NODES_MAX 100000
#define EDGES_MAX 1600000
#define GRAPHS 64
#define EPS 1e-5f

// -------- scratch (static __device__ arrays; no allocation allowed) --------
__device__ float d_agg[(size_t)NODES_MAX * 128];   // mean-aggregated features
__device__ float d_h1 [(size_t)NODES_MAX * 128];
__device__ float d_h2 [(size_t)NODES_MAX * 128];
__device__ int   d_deg [NODES_MAX];
__device__ int   d_rowp[NODES_MAX + 1];
__device__ int   d_curs[NODES_MAX];
__device__ int   d_csr [EDGES_MAX];
// pre-split weights, stacked [Wl;Wr] along K: Wb[n][k], k in [0,256)
__device__ __nv_bfloat16 d_w1hi[128 * 256];
__device__ __nv_bfloat16 d_w1lo[128 * 256];
__device__ __nv_bfloat16 d_w2hi[256 * 256];
__device__ __nv_bfloat16 d_w2lo[256 * 256];

// ---------------------------------------------------------------------------
// baseline-PTX helpers (compute_103-safe: sm_75/80 features only)
// ---------------------------------------------------------------------------
__device__ __forceinline__ uint32_t smem_to_u32(const void* p) {
    uint32_t a;
    asm("{ .reg .u64 t; cvta.to.shared.u64 t, %1; cvt.u32.u64 %0, t; }"
        : "=r"(a) : "l"(p));
    return a;
}
__device__ __forceinline__ void ldsm_x4(uint32_t* r, uint32_t addr) {
    asm volatile("ldmatrix.sync.aligned.m8n8.x4.shared.b16 {%0,%1,%2,%3}, [%4];"
                 : "=r"(r[0]), "=r"(r[1]), "=r"(r[2]), "=r"(r[3]) : "r"(addr));
}
__device__ __forceinline__ void ldsm_x2(uint32_t* r, uint32_t addr) {
    asm volatile("ldmatrix.sync.aligned.m8n8.x2.shared.b16 {%0,%1}, [%2];"
                 : "=r"(r[0]), "=r"(r[1]) : "r"(addr));
}
__device__ __forceinline__ void mma_bf16(float* c, const uint32_t* a, const uint32_t* b) {
    asm volatile("mma.sync.aligned.m16n8k16.row.col.f32.bf16.bf16.f32 "
                 "{%0,%1,%2,%3}, {%4,%5,%6,%7}, {%8,%9}, {%0,%1,%2,%3};"
                 : "+f"(c[0]), "+f"(c[1]), "+f"(c[2]), "+f"(c[3])
                 : "r"(a[0]), "r"(a[1]), "r"(a[2]), "r"(a[3]), "r"(b[0]), "r"(b[1]));
}

// ---------------------------------------------------------------------------
// zero-fill
// ---------------------------------------------------------------------------
__global__ void zero4_kernel(float4* __restrict__ p, size_t n4) {
    size_t i = (size_t)blockIdx.x * blockDim.x + threadIdx.x;
    size_t stride = (size_t)gridDim.x * blockDim.x;
    float4 z = make_float4(0.f, 0.f, 0.f, 0.f);
    for (; i < n4; i += stride) p[i] = z;
}

// ---------------------------------------------------------------------------
// weight prep: Wb[n][k] = (k<128 ? Wl[k][n] : Wr[k-128][n]) split into bf16 hi/lo
// ---------------------------------------------------------------------------
__global__ void prep_w_kernel(const float* __restrict__ Wl, const float* __restrict__ Wr,
                              __nv_bfloat16* __restrict__ hi, __nv_bfloat16* __restrict__ lo,
                              int dout) {
    int idx = blockIdx.x * blockDim.x + threadIdx.x;
    if (idx >= dout * 256) return;
    int nn = idx >> 8, k = idx & 255;
    float w = (k < 128) ? Wl[k * dout + nn] : Wr[(k - 128) * dout + nn];
    __nv_bfloat16 h = __float2bfloat16(w);
    hi[idx] = h;
    lo[idx] = __float2bfloat16(w - __bfloat162float(h));
}

// ---------------------------------------------------------------------------
// CSR build: histogram -> single-block scan -> fill (cursor = copy of rowp)
// ---------------------------------------------------------------------------
__global__ void hist_kernel(const int* __restrict__ ei, int E, int n) {
    int e = blockIdx.x * blockDim.x + threadIdx.x;
    if (e >= E) return;
    int s = ei[e];
    int d = ei[(size_t)E + e];
    if ((unsigned)s >= (unsigned)n || (unsigned)d >= (unsigned)n) return;
    atomicAdd(&d_deg[d], 1);
}

#define SCAN_T 1024
__global__ void __launch_bounds__(SCAN_T)
scan_kernel(int n) {
    __shared__ int s[SCAN_T];
    int tid = threadIdx.x;
    int per = (n + SCAN_T - 1) / SCAN_T;
    int start = tid * per;
    int end = min(start + per, n);
    int sum = 0;
    for (int i = start; i < end; i++) sum += d_deg[i];
    s[tid] = sum;
    __syncthreads();
    for (int off = 1; off < SCAN_T; off <<= 1) {
        int v = (tid >= off) ? s[tid - off] : 0;
        __syncthreads();
        s[tid] += v;
        __syncthreads();
    }
    int run = (tid > 0) ? s[tid - 1] : 0;
    for (int i = start; i < end; i++) { d_rowp[i] = run; run += d_deg[i]; }
    if (tid == SCAN_T - 1) d_rowp[n] = s[SCAN_T - 1];
}

__global__ void fill_kernel(const int* __restrict__ ei, int E, int n) {
    int e = blockIdx.x * blockDim.x + threadIdx.x;
    if (e >= E) return;
    int s = ei[e];
    int d = ei[(size_t)E + e];
    if ((unsigned)s >= (unsigned)n || (unsigned)d >= (unsigned)n) return;
    int pos = atomicAdd(&d_curs[d], 1);
    if (pos < EDGES_MAX) d_csr[pos] = s;
}

// ---------------------------------------------------------------------------
// Layer-0 gather: 8 threads per node (7 active features). Writes MEAN into
// stride-8 agg rows.
// ---------------------------------------------------------------------------
__global__ void gather7_kernel(const float* __restrict__ x, int n) {
    int idx = blockIdx.x * blockDim.x + threadIdx.x;
    int node = idx >> 3;
    int j = idx & 7;
    if (node >= n) return;
    int b = d_rowp[node], e = d_rowp[node + 1];
    float acc = 0.f;
    if (j < 7) {
        int i = b;
        for (; i + 1 < e; i += 2) {
            int s0 = d_csr[i], s1 = d_csr[i + 1];
            acc += x[(size_t)s0 * 7 + j] + x[(size_t)s1 * 7 + j];
        }
        if (i < e) acc += x[(size_t)d_csr[i] * 7 + j];
    }
    float inv = 1.0f / (float)max(e - b, 1);
    d_agg[(size_t)node * 8 + j] = acc * inv;   // j==7 writes 0 (padding)
}

// ---------------------------------------------------------------------------
// din=128 gather: one warp per node; lane owns 4 consecutive features.
// Unroll-2 over neighbors for MLP. Writes MEAN (no atomics, no zero pass).
// ---------------------------------------------------------------------------
__global__ void gather128_kernel(const float* __restrict__ feat, int n) {
    int idx = blockIdx.x * blockDim.x + threadIdx.x;
    int node = idx >> 5;
    int lane = idx & 31;
    if (node >= n) return;
    int b = d_rowp[node], e = d_rowp[node + 1];
    float4 a0 = make_float4(0.f, 0.f, 0.f, 0.f);
    float4 a1 = a0;
    int i = b;
    for (; i + 1 < e; i += 2) {
        int s0 = d_csr[i], s1 = d_csr[i + 1];
        float4 v0 = reinterpret_cast<const float4*>(feat + (size_t)s0 * 128)[lane];
        float4 v1 = reinterpret_cast<const float4*>(feat + (size_t)s1 * 128)[lane];
        a0.x += v0.x; a0.y += v0.y; a0.z += v0.z; a0.w += v0.w;
        a1.x += v1.x; a1.y += v1.y; a1.z += v1.z; a1.w += v1.w;
    }
    if (i < e) {
        float4 v = reinterpret_cast<const float4*>(feat + (size_t)d_csr[i] * 128)[lane];
        a0.x += v.x; a0.y += v.y; a0.z += v.z; a0.w += v.w;
    }
    float inv = 1.0f / (float)max(e - b, 1);
    float4 m = make_float4((a0.x + a1.x) * inv, (a0.y + a1.y) * inv,
                           (a0.z + a1.z) * inv, (a0.w + a1.w) * inv);
    reinterpret_cast<float4*>(d_agg + (size_t)node * 128)[lane] = m;
}

// ---------------------------------------------------------------------------
// Layer 0: din=7 -> dout=128. 32 nodes/block; weights staged in smem.
// d_agg already holds the MEAN.
// ---------------------------------------------------------------------------
#define G0_NODES 32
__global__ void __launch_bounds__(128)
gemm0_kernel(const float* __restrict__ x,
             const float* __restrict__ Wl, const float* __restrict__ bl,
             const float* __restrict__ Wr,
             const float* __restrict__ g,  const float* __restrict__ be,
             const float* __restrict__ rm, const float* __restrict__ rv,
             int n) {
    __shared__ float sW0[7][128];
    __shared__ float sW1[7][128];
    __shared__ float sx[G0_NODES][8];
    __shared__ float sm[G0_NODES][8];
    int tid = threadIdx.x;
    int node0 = blockIdx.x * G0_NODES;
#pragma unroll
    for (int k = 0; k < 7; k++) {
        sW0[k][tid] = Wl[k * 128 + tid];
        sW1[k][tid] = Wr[k * 128 + tid];
    }
    for (int i = tid; i < G0_NODES * 7; i += 128) {
        int ni = i / 7, k = i % 7;
        int node = node0 + ni;
        float xv = 0.f, mv = 0.f;
        if (node < n) {
            xv = x[(size_t)node * 7 + k];
            mv = d_agg[(size_t)node * 8 + k];
        }
        sx[ni][k] = xv;
        sm[ni][k] = mv;
    }
    __syncthreads();
    int j = tid;
    float s = g[j] * rsqrtf(rv[j] + EPS);
    float t = be[j] + (bl[j] - rm[j]) * s;
#pragma unroll 4
    for (int ni = 0; ni < G0_NODES; ni++) {
        int node = node0 + ni;
        if (node >= n) break;
        float acc = 0.f;
#pragma unroll
        for (int k = 0; k < 7; k++)
            acc += sx[ni][k] * sW0[k][j] + sm[ni][k] * sW1[k][j];
        d_h1[(size_t)node * 128 + j] = fmaxf(acc * s + t, 0.0f);
    }
}

// ---------------------------------------------------------------------------
// bf16 split-precision GEMM via mma.sync (layers 1/2).
//   C[m][col0+j] = relu(BN( sum_k Afull[m][k] * Wb[col0+j][k] ))
// Afull = [h | mean], K=256 in 8 chunks of 32 (d_agg already mean-scaled).
// D += Ah*Bh + Ah*Bl + Al*Bh  (fp32 accumulators; Al*Bl dropped, ~2^-16 rel).
// Tile 128x128, 8 warps (2m x 4n), warp tile 64x32 of m16n8k16 fragments.
// ---------------------------------------------------------------------------
#define AST 40

template <int DOUT>
__global__ void __launch_bounds__(256)
gemm_mma_kernel(const float* __restrict__ A,
                const __nv_bfloat16* __restrict__ WbHi,
                const __nv_bfloat16* __restrict__ WbLo,
                const float* __restrict__ bl,
                const float* __restrict__ g,  const float* __restrict__ be,
                const float* __restrict__ rm, const float* __restrict__ rv,
                float* __restrict__ C, int n) {
    __shared__ __align__(16) __nv_bfloat16 sAh[128 * AST];
    __shared__ __align__(16) __nv_bfloat16 sAl[128 * AST];
    __shared__ __align__(16) __nv_bfloat16 sBh[128 * AST];
    __shared__ __align__(16) __nv_bfloat16 sBl[128 * AST];
    __shared__ float sS[128], sT[128];

    int tid  = threadIdx.x;
    int lane = tid & 31;
    int wid  = tid >> 5;
    int row0 = blockIdx.x * 128;
    int col0 = blockIdx.y * 128;
    int wm = wid & 1;
    int wn = wid >> 1;

    if (tid < 128) {
        int col = col0 + tid;
        float s = g[col] * rsqrtf(rv[col] + EPS);
        sS[tid] = s;
        sT[tid] = be[col] + (bl[col] - rm[col]) * s;
    }

    uint32_t uAh = smem_to_u32(sAh), uAl = smem_to_u32(sAl);
    uint32_t uBh = smem_to_u32(sBh), uBl = smem_to_u32(sBl);

    float acc[4][4][4];
#pragma unroll
    for (int mt = 0; mt < 4; mt++)
#pragma unroll
        for (int nt = 0; nt < 4; nt++)
#pragma unroll
            for (int q = 0; q < 4; q++) acc[mt][nt][q] = 0.f;

    int ra = (lane & 7) + ((lane >> 3) & 1) * 8;
    int kaH = ((lane >> 4) & 1) * 8;
    int rb = lane & 7;
    int kbH = ((lane >> 3) & 1) * 8;

#pragma unroll 1
    for (int c = 0; c < 8; ++c) {
        __syncthreads();
        // ---- stage A chunk [128 rows x 32 k] f32 -> bf16 hi/lo ----
#pragma unroll
        for (int it = 0; it < 4; ++it) {
            int q   = tid + it * 256;
            int row = q >> 3;
            int k4  = (q & 7) * 4;
            int rg  = row0 + row;
            float4 f = make_float4(0.f, 0.f, 0.f, 0.f);
            if (rg < n) {
                const float* src = (c < 4)
                    ? A     + (size_t)rg * 128 +  c      * 32 + k4
                    : d_agg + (size_t)rg * 128 + (c - 4) * 32 + k4;
                f = *(const float4*)src;
            }
            __nv_bfloat162 h0 = __float22bfloat162_rn(make_float2(f.x, f.y));
            __nv_bfloat162 h1 = __float22bfloat162_rn(make_float2(f.z, f.w));
            float2 hf0 = __bfloat1622float2(h0);
            float2 hf1 = __bfloat1622float2(h1);
            __nv_bfloat162 l0 = __float22bfloat162_rn(make_float2(f.x - hf0.x, f.y - hf0.y));
            __nv_bfloat162 l1 = __float22bfloat162_rn(make_float2(f.z - hf1.x, f.w - hf1.y));
            uint32_t off = row * AST + k4;
            *(uint2*)(sAh + off) = make_uint2(*(uint32_t*)&h0, *(uint32_t*)&h1);
            *(uint2*)(sAl + off) = make_uint2(*(uint32_t*)&l0, *(uint32_t*)&l1);
        }
        // ---- stage B chunk [128 n x 32 k] (pre-split bf16 in gmem) ----
#pragma unroll
        for (int it = 0; it < 2; ++it) {
            int q  = tid + it * 256;
            int nl = q >> 2;
            int k8 = (q & 3) * 8;
            size_t src = (size_t)(col0 + nl) * 256 + c * 32 + k8;
            uint4 h = *(const uint4*)(WbHi + src);
            uint4 l = *(const uint4*)(WbLo + src);
            uint32_t off = nl * AST + k8;
            *(uint4*)(sBh + off) = h;
            *(uint4*)(sBl + off) = l;
        }
        __syncthreads();
        // ---- compute: 2 K=16 steps x (4m x 4n) fragments x 3 split terms ----
#pragma unroll
        for (int ks = 0; ks < 32; ks += 16) {
            uint32_t ah[4][4], al[4][4], bh[4][2], blo[4][2];
#pragma unroll
            for (int mt = 0; mt < 4; ++mt) {
                uint32_t off = ((wm * 64 + mt * 16 + ra) * AST + ks + kaH) * 2;
                ldsm_x4(ah[mt], uAh + off);
                ldsm_x4(al[mt], uAl + off);
            }
#pragma unroll
            for (int nt = 0; nt < 4; ++nt) {
                uint32_t off = ((wn * 32 + nt * 8 + rb) * AST + ks + kbH) * 2;
                ldsm_x2(bh[nt],  uBh + off);
                ldsm_x2(blo[nt], uBl + off);
            }
#pragma unroll
            for (int mt = 0; mt < 4; ++mt)
#pragma unroll
                for (int nt = 0; nt < 4; ++nt) {
                    mma_bf16(acc[mt][nt], ah[mt], bh[nt]);
                    mma_bf16(acc[mt][nt], ah[mt], blo[nt]);
                    mma_bf16(acc[mt][nt], al[mt], bh[nt]);
                }
        }
    }

    // ---- epilogue: BN + ReLU fused on fragments ----
#pragma unroll
    for (int mt = 0; mt < 4; ++mt) {
        int rbase = row0 + wm * 64 + mt * 16 + (lane >> 2);
#pragma unroll
        for (int nt = 0; nt < 4; ++nt) {
            int cl = wn * 32 + nt * 8 + 2 * (lane & 3);
            float s0 = sS[cl], s1 = sS[cl + 1];
            float t0 = sT[cl], t1 = sT[cl + 1];
            if (rbase < n) {
                float2 o = make_float2(fmaxf(acc[mt][nt][0] * s0 + t0, 0.f),
                                       fmaxf(acc[mt][nt][1] * s1 + t1, 0.f));
                *(float2*)(C + (size_t)rbase * DOUT + col0 + cl) = o;
            }
            if (rbase + 8 < n) {
                float2 o = make_float2(fmaxf(acc[mt][nt][2] * s0 + t0, 0.f),
                                       fmaxf(acc[mt][nt][3] * s1 + t1, 0.f));
                *(float2*)(C + (size_t)(rbase + 8) * DOUT + col0 + cl) = o;
            }
        }
    }
}

// ---------------------------------------------------------------------------
// global_add_pool (batch sorted)
// ---------------------------------------------------------------------------
#define POOL_ROWS 512
__global__ void pool_kernel(const float* __restrict__ xf,
                            const int* __restrict__ batch,
                            float* __restrict__ pooled, int n) {
    int j  = threadIdx.x;
    int r0 = blockIdx.x * POOL_ROWS;
    if (r0 >= n) return;
    int r1 = min(r0 + POOL_ROWS, n);
    int cur = batch[r0];
    float acc = 0.0f;
    for (int r = r0; r < r1; ++r) {
        int b = batch[r];
        if (b != cur) {
            if ((unsigned)cur < GRAPHS) atomicAdd(&pooled[cur * 256 + j], acc);
            acc = 0.0f;
            cur = b;
        }
        acc += xf[(size_t)r * 256 + j];
    }
    if ((unsigned)cur < GRAPHS) atomicAdd(&pooled[cur * 256 + j], acc);
}

// ---------------------------------------------------------------------------
// launch
// ---------------------------------------------------------------------------
extern "C" void kernel_launch(void* const* d_in, const int* in_sizes, int n_in,
                              void* d_out, int out_size) {
    const float* x     = (const float*)d_in[0];
    const int*   ei    = (const int*)d_in[1];
    const int*   batch = (const int*)d_in[2];

    const float* Wl0 = (const float*)d_in[3];
    const float* bl0 = (const float*)d_in[4];
    const float* Wr0 = (const float*)d_in[5];
    const float* g0  = (const float*)d_in[6];
    const float* be0 = (const float*)d_in[7];
    const float* rm0 = (const float*)d_in[8];
    const float* rv0 = (const float*)d_in[9];

    const float* Wl1 = (const float*)d_in[10];
    const float* bl1 = (const float*)d_in[11];
    const float* Wr1 = (const float*)d_in[12];
    const float* g1  = (const float*)d_in[13];
    const float* be1 = (const float*)d_in[14];
    const float* rm1 = (const float*)d_in[15];
    const float* rv1 = (const float*)d_in[16];

    const float* Wl2 = (const float*)d_in[17];
    const float* bl2 = (const float*)d_in[18];
    const float* Wr2 = (const float*)d_in[19];
    const float* g2  = (const float*)d_in[20];
    const float* be2 = (const float*)d_in[21];
    const float* rm2 = (const float*)d_in[22];
    const float* rv2 = (const float*)d_in[23];

    const int E = in_sizes[1] / 2;
    const int n = in_sizes[2];

    float* out    = (float*)d_out;
    float* pooled = out;                        // [64, 256]
    float* xout   = out + (size_t)GRAPHS * 256; // [n, 256]

    float *h1 = nullptr, *h2 = nullptr;
    int *deg = nullptr, *rowp = nullptr, *curs = nullptr;
    cudaGetSymbolAddress((void**)&h1,   d_h1);
    cudaGetSymbolAddress((void**)&h2,   d_h2);
    cudaGetSymbolAddress((void**)&deg,  d_deg);
    cudaGetSymbolAddress((void**)&rowp, d_rowp);
    cudaGetSymbolAddress((void**)&curs, d_curs);
    __nv_bfloat16 *w1h, *w1l, *w2h, *w2l;
    cudaGetSymbolAddress((void**)&w1h, d_w1hi);
    cudaGetSymbolAddress((void**)&w1l, d_w1lo);
    cudaGetSymbolAddress((void**)&w2h, d_w2hi);
    cudaGetSymbolAddress((void**)&w2l, d_w2lo);

    int mtiles = (n + 127) / 128;

    // ---- weight prep (tiny) ----
    prep_w_kernel<<<(128 * 256 + 255) / 256, 256>>>(Wl1, Wr1, w1h, w1l, 128);
    prep_w_kernel<<<(256 * 256 + 255) / 256, 256>>>(Wl2, Wr2, w2h, w2l, 256);

    // ---- CSR build (amortized over all 3 aggregation passes) ----
    zero4_kernel<<<64, 256>>>((float4*)deg, (size_t)n / 4);
    zero4_kernel<<<16, 256>>>((float4*)pooled, (size_t)GRAPHS * 64);
    hist_kernel<<<(E + 255) / 256, 256>>>(ei, E, n);
    scan_kernel<<<1, SCAN_T>>>(n);
    cudaMemcpyAsync(curs, rowp, (size_t)n * sizeof(int), cudaMemcpyDeviceToDevice);
    fill_kernel<<<(E + 255) / 256, 256>>>(ei, E, n);

    // ---- layer 0 ----
    gather7_kernel<<<(n * 8 + 255) / 256, 256>>>(x, n);
    gemm0_kernel<<<(n + G0_NODES - 1) / G0_NODES, 128>>>(
        x, Wl0, bl0, Wr0, g0, be0, rm0, rv0, n);

    // ---- layer 1 ----
    gather128_kernel<<<(n + 7) / 8, 256>>>(h1, n);
    gemm_mma_kernel<128><<<dim3(mtiles, 1), 256>>>(
        h1, w1h, w1l, bl1, g1, be1, rm1, rv1, h2, n);

    // ---- layer 2 (writes x-output directly into d_out) ----
    gather128_kernel<<<(n + 7) / 8, 256>>>(h2, n);
    gemm_mma_kernel<256><<<dim3(mtiles, 2), 256>>>(
        h2, w2h, w2l, bl2, g2, be2, rm2, rv2, xout, n);

    // ---- global add pool ----
    pool_kernel<<<(n + POOL_ROWS - 1) / POOL_ROWS, 256>>>(xout, batch, pooled, n);
}